// round 10
// baseline (speedup 1.0000x reference)
#include <cuda_runtime.h>
#include <math.h>

#define BB 32
#define SS 400
#define TT 100
#define EE 256
#define HE 256
#define HD 512
#define VV 32000

// ---------------- scratch (device globals; no allocations) ----------------
__device__ float g_srcx[SS * BB * EE];
__device__ float g_trgx[TT * BB * EE];
__device__ float g_gif[SS * BB * 3 * HE];
__device__ float g_gib[SS * BB * 3 * HE];
__device__ float g_gidec[TT * BB * 3 * HD];
__device__ float g_enhy[BB * SS * 2 * HE];
__device__ float g_hT[2][2][HE * BB];     // [dir][parity][u*BB + b] (transposed)
__device__ float g_hcat[BB * 2 * HE];
__device__ float g_hdec[2][BB * HD];
__device__ float g_ctx[BB * HD];
__device__ float g_decout[BB * TT * HD];
__device__ float g_attm[4][BB];
__device__ float g_attl[4][BB];
__device__ float g_attc[4][BB][HD];
__device__ unsigned g_bar_cnt[4];         // 0=enc dir0, 1=enc dir1, 2=dec

// ---------------- cheap monotonic grid barrier (tid0-only polling) ----------------
__device__ __forceinline__ void bar_sync(unsigned* cnt, unsigned target) {
    __syncthreads();
    if (threadIdx.x == 0) {
        unsigned p;
        asm volatile("atom.release.gpu.global.add.u32 %0,[%1],%2;"
                     : "=r"(p) : "l"(cnt), "r"(1u) : "memory");
        if (p + 1u < target) {
            unsigned v;
            for (;;) {
                asm volatile("ld.acquire.gpu.global.u32 %0,[%1];" : "=r"(v) : "l"(cnt) : "memory");
                if (v >= target) break;
                __nanosleep(32);
            }
        }
    }
    __syncthreads();
}

// ---------------- embedding gather ----------------
__global__ void embed_kernel(const int* __restrict__ ids, const float* __restrict__ table,
                             float* __restrict__ out, int seq) {
    int i = blockIdx.x * blockDim.x + threadIdx.x;
    int E4 = EE / 4;
    int total = seq * BB * E4;
    if (i >= total) return;
    int e4 = i % E4;
    int sb = i / E4;
    int b = sb % BB;
    int s = sb / BB;
    int id = ids[b * seq + s];
    ((float4*)out)[i] = ((const float4*)table)[(size_t)id * E4 + e4];
}

// ---------------- prep ----------------
__global__ void prep_kernel() {
    int i = blockIdx.x * blockDim.x + threadIdx.x;
    if (i < 4) g_bar_cnt[i] = 0u;
    if (i < 2 * BB * HE) g_hT[i / (BB * HE)][0][i % (BB * HE)] = 0.f;
}

// ---------------- tf32 -> bits ----------------
__device__ __forceinline__ unsigned f2t(float x) {
    unsigned r; asm("cvt.rna.tf32.f32 %0, %1;" : "=r"(r) : "f"(x)); return r;
}

// ---------------- tf32 GEMM v6: 128x128 CTA tile, 4 warps, 64x64 warp tile ----------------
// C = A(M,K)*B(N,K)^T + bias. Double-buffered smem, one sync per k16.
// 2x FLOP per LDS byte vs 32x32 warp tiles (the measured L1/shared bottleneck).
template<int KK>
__global__ void __launch_bounds__(128) gemm_tf32(
    const float* __restrict__ A, const float* __restrict__ Bm,
    const float* __restrict__ bias, float* __restrict__ C,
    int M, int N, int ldb)
{
    constexpr int NT = KK / 16;
    __shared__ unsigned sA[2][16][136];
    __shared__ unsigned sB[2][16][136];
    int bm = blockIdx.y * 128, bn = blockIdx.x * 128;
    int tid = threadIdx.x;            // 0..127
    int w = tid >> 5, lane = tid & 31;
    int wm = w & 1, wn = w >> 1;      // 2x2 warp grid
    int g = lane >> 2, tg = lane & 3;
    const float* Ap = A + (size_t)(bm + tid) * KK;
    const float* Bp = Bm + (size_t)(bn + tid) * ldb;

    // ---- stage tile 0 ----
    {
        float4 va[4], vb[4];
#pragma unroll
        for (int q = 0; q < 4; q++) {
            va[q] = *(const float4*)(Ap + q * 4);
            vb[q] = *(const float4*)(Bp + q * 4);
        }
#pragma unroll
        for (int q = 0; q < 4; q++) {
            const float* pa = &va[q].x;
            const float* pb = &vb[q].x;
#pragma unroll
            for (int cc = 0; cc < 4; cc++) {
                sA[0][q * 4 + cc][tid] = f2t(pa[cc]);
                sB[0][q * 4 + cc][tid] = f2t(pb[cc]);
            }
        }
    }
    __syncthreads();

    float d[4][8][4];
#pragma unroll
    for (int f = 0; f < 4; f++)
#pragma unroll
        for (int j = 0; j < 8; j++)
#pragma unroll
            for (int e = 0; e < 4; e++) d[f][j][e] = 0.f;

    int mr0 = wm * 64 + g;
    int nc0 = wn * 64 + g;

#pragma unroll 2
    for (int i = 0; i < NT; i++) {
        const int st = i & 1;
        // ---- load ALL fragments for this k16 ----
        unsigned a[2][4][4], bf[2][8][2];
#pragma unroll
        for (int kh = 0; kh < 2; kh++) {
            int kk = kh * 8;
#pragma unroll
            for (int f = 0; f < 4; f++) {
                int mr = mr0 + f * 16;
                a[kh][f][0] = sA[st][kk + tg][mr];
                a[kh][f][1] = sA[st][kk + tg][mr + 8];
                a[kh][f][2] = sA[st][kk + tg + 4][mr];
                a[kh][f][3] = sA[st][kk + tg + 4][mr + 8];
            }
#pragma unroll
            for (int j = 0; j < 8; j++) {
                int nc = nc0 + j * 8;
                bf[kh][j][0] = sB[st][kk + tg][nc];
                bf[kh][j][1] = sB[st][kk + tg + 4][nc];
            }
        }
        // ---- LDG next tile (latency hidden under 64 MMAs) ----
        float4 na[4], nb[4];
        if (i + 1 < NT) {
#pragma unroll
            for (int q = 0; q < 4; q++) {
                na[q] = *(const float4*)(Ap + (i + 1) * 16 + q * 4);
                nb[q] = *(const float4*)(Bp + (i + 1) * 16 + q * 4);
            }
        }
        // ---- 64 MMAs ----
#pragma unroll
        for (int kh = 0; kh < 2; kh++)
#pragma unroll
            for (int f = 0; f < 4; f++)
#pragma unroll
                for (int j = 0; j < 8; j++)
                    asm volatile(
                        "mma.sync.aligned.m16n8k8.row.col.f32.tf32.tf32.f32 "
                        "{%0,%1,%2,%3}, {%4,%5,%6,%7}, {%8,%9}, {%0,%1,%2,%3};"
                        : "+f"(d[f][j][0]), "+f"(d[f][j][1]),
                          "+f"(d[f][j][2]), "+f"(d[f][j][3])
                        : "r"(a[kh][f][0]), "r"(a[kh][f][1]), "r"(a[kh][f][2]), "r"(a[kh][f][3]),
                          "r"(bf[kh][j][0]), "r"(bf[kh][j][1]));
        // ---- STS next tile into other stage ----
        if (i + 1 < NT) {
            const int ns = st ^ 1;
#pragma unroll
            for (int q = 0; q < 4; q++) {
                const float* pa = &na[q].x;
                const float* pb = &nb[q].x;
#pragma unroll
                for (int cc = 0; cc < 4; cc++) {
                    sA[ns][q * 4 + cc][tid] = f2t(pa[cc]);
                    sB[ns][q * 4 + cc][tid] = f2t(pb[cc]);
                }
            }
        }
        __syncthreads();
    }
    // ---- epilogue ----
#pragma unroll
    for (int f = 0; f < 4; f++) {
        int r0 = bm + wm * 64 + f * 16 + g;
#pragma unroll
        for (int j = 0; j < 8; j++) {
            int col = bn + wn * 64 + j * 8 + tg * 2;
            float b0 = __ldg(&bias[col]), b1 = __ldg(&bias[col + 1]);
            float2 v0 = make_float2(d[f][j][0] + b0, d[f][j][1] + b1);
            float2 v1 = make_float2(d[f][j][2] + b0, d[f][j][3] + b1);
            *(float2*)&C[(size_t)r0 * N + col] = v0;
            *(float2*)&C[(size_t)(r0 + 8) * N + col] = v1;
        }
    }
}

// ---------------- small fp32 GEMM (e2d only, M=32, tanh) ----------------
__global__ void __launch_bounds__(256) gemm_atb(
    const float* __restrict__ A, const float* __restrict__ Bm,
    const float* __restrict__ bias, float* __restrict__ C,
    int M, int N, int K, int ldb, int act)
{
    __shared__ float sA[16][68];
    __shared__ float sB[16][68];
    int bm = blockIdx.y * 64, bn = blockIdx.x * 64;
    int tid = threadIdx.x;
    int tm = (tid >> 4) << 2, tn = (tid & 15) << 2;
    int lr = tid >> 2, lc = (tid & 3) << 2;
    float acc[4][4] = {};
    for (int k0 = 0; k0 < K; k0 += 16) {
        float4 a4 = make_float4(0.f, 0.f, 0.f, 0.f);
        if (bm + lr < M) a4 = *(const float4*)&A[(size_t)(bm + lr) * K + k0 + lc];
        sA[lc + 0][lr] = a4.x; sA[lc + 1][lr] = a4.y; sA[lc + 2][lr] = a4.z; sA[lc + 3][lr] = a4.w;
        float4 b4 = *(const float4*)&Bm[(size_t)(bn + lr) * ldb + k0 + lc];
        sB[lc + 0][lr] = b4.x; sB[lc + 1][lr] = b4.y; sB[lc + 2][lr] = b4.z; sB[lc + 3][lr] = b4.w;
        __syncthreads();
#pragma unroll
        for (int kk = 0; kk < 16; kk++) {
            float4 av = *(const float4*)&sA[kk][tm];
            float4 bv = *(const float4*)&sB[kk][tn];
            float a[4] = {av.x, av.y, av.z, av.w};
            float b[4] = {bv.x, bv.y, bv.z, bv.w};
#pragma unroll
            for (int i = 0; i < 4; i++)
#pragma unroll
                for (int j = 0; j < 4; j++) acc[i][j] += a[i] * b[j];
        }
        __syncthreads();
    }
#pragma unroll
    for (int i = 0; i < 4; i++) {
        int row = bm + tm + i;
        if (row >= M) continue;
        float4 v;
        float* pv = &v.x;
#pragma unroll
        for (int j = 0; j < 4; j++) {
            float x = acc[i][j] + bias[bn + tn + j];
            if (act == 1) x = tanhf(x);
            pv[j] = x;
        }
        *(float4*)&C[(size_t)row * N + bn + tn] = v;
    }
}

// ---------------- persistent encoder (proven R7 version): 64 CTAs x 256 thr ----------------
__global__ void __launch_bounds__(256) enc_persist(
    const float* __restrict__ Whh_f, const float* __restrict__ Whh_b,
    const float* __restrict__ bhh_f, const float* __restrict__ bhh_b)
{
    extern __shared__ float es[];
    float* swt = es;            // [3*8*256]
    float* sh  = es + 6144;     // [32][260]
    int c = blockIdx.x;
    int dir = c >> 5;
    int ublk = c & 31;
    int tid = threadIdx.x;
    int b = tid & 31;
    int ul = tid >> 5;
    int u = ublk * 8 + ul;
    const float* Whh = dir ? Whh_b : Whh_f;
    const float* bhh = dir ? bhh_b : bhh_f;
    const float* gibase = dir ? g_gib : g_gif;
    for (int i = tid; i < 6144; i += 256) {
        int gate = i >> 11;
        int rem = i & 2047;
        swt[i] = Whh[((size_t)gate * HE + ublk * 8 + (rem >> 8)) * HE + (rem & 255)];
    }
    float br_ = bhh[u], bz_ = bhh[HE + u], bn_ = bhh[2 * HE + u];
    const float4* wr = (const float4*)&swt[(0 * 8 + ul) * 256];
    const float4* wz = (const float4*)&swt[(1 * 8 + ul) * 256];
    const float4* wn = (const float4*)&swt[(2 * 8 + ul) * 256];
    unsigned* cnt = &g_bar_cnt[dir];
    const float* hb = sh + b * 260;

    for (int t = 0; t < SS; t++) {
        if (t > 0) bar_sync(cnt, (unsigned)(32 * t));
        const float* hsrc = g_hT[dir][t & 1];
        for (int i = tid; i < BB * HE; i += 256)
            sh[(i & 31) * 260 + (i >> 5)] = __ldcg(&hsrc[i]);
        __syncthreads();
        float ar = 0.f, az = 0.f, an = 0.f;
#pragma unroll 8
        for (int k4 = 0; k4 < 64; k4++) {
            float4 h4 = *(const float4*)(hb + k4 * 4);
            float4 ww;
            ww = wr[k4]; ar += h4.x * ww.x + h4.y * ww.y + h4.z * ww.z + h4.w * ww.w;
            ww = wz[k4]; az += h4.x * ww.x + h4.y * ww.y + h4.z * ww.z + h4.w * ww.w;
            ww = wn[k4]; an += h4.x * ww.x + h4.y * ww.y + h4.z * ww.z + h4.w * ww.w;
        }
        int s = dir ? (SS - 1 - t) : t;
        const float* gi = gibase + (size_t)(s * BB + b) * (3 * HE);
        float ghr = ar + br_, ghz = az + bz_, ghn = an + bn_;
        float r = 1.f / (1.f + expf(-(__ldg(&gi[u]) + ghr)));
        float z = 1.f / (1.f + expf(-(__ldg(&gi[HE + u]) + ghz)));
        float n = tanhf(__ldg(&gi[2 * HE + u]) + r * ghn);
        float hp = hb[u];
        float hn2 = (1.f - z) * n + z * hp;
        g_hT[dir][(t + 1) & 1][u * BB + b] = hn2;
        g_enhy[((size_t)b * SS + s) * (2 * HE) + dir * HE + u] = hn2;
        __syncthreads();
    }
}

// ---------------- build [hT_f, hT_b] ----------------
__global__ void hcat_kernel() {
    int i = blockIdx.x * blockDim.x + threadIdx.x;
    if (i >= BB * 2 * HE) return;
    int b = i >> 9;
    int j = i & 511;
    float v;
    if (j < HE) v = g_enhy[((size_t)b * SS + (SS - 1)) * (2 * HE) + j];
    else        v = g_enhy[((size_t)b * SS + 0) * (2 * HE) + j];
    g_hcat[i] = v;
}

// ---------------- persistent decoder (R9 version): 128 CTAs x 512 thr ----------------
__global__ void __launch_bounds__(512) dec_persist(
    const float* __restrict__ dWih, const float* __restrict__ dWhh,
    const float* __restrict__ dbhh)
{
    extern __shared__ float sm[];
    float* swd    = sm;                 // [12288]
    float* shh    = sm + 12288;         // [32][516]
    float* shc    = sm + 28800;         // [32][516]
    float* smx    = sm + 45312;         // [9*132]
    float* sm_m   = sm + 46500;         // [16]
    float* sm_l   = sm + 46516;         // [16]
    float* sm_ctx = sm + 46532;         // [16*512]  total 54724 floats

    int c = blockIdx.x;
    int tid = threadIdx.x;
    int lane = tid & 31, w = tid >> 5;
    int ab = c & 31, chunk = c >> 5, s0 = chunk * (SS / 4);
    int gb = tid & 31;
    int slot = (tid >> 5) & 3;
    int which = tid >> 7;
    int gu = c * 4 + slot;

    for (int i = tid; i < 12288; i += 512) {
        int sg = i >> 11;
        int rem = i & 2047;
        int sl = rem >> 9;
        int k = rem & 511;
        int s_ = sg / 3, g2 = sg % 3;
        int uu = c * 4 + sl;
        swd[i] = (s_ == 0) ? dWhh[((size_t)g2 * HD + uu) * HD + k]
                           : dWih[((size_t)(g2 * HD + uu)) * 768 + 256 + k];
    }
    int ws = which >> 1;
    int kb = (which & 1) * 256;
    const float4* vr = (const float4*)&swd[((ws * 3 + 0) * 4 + slot) * 512 + kb];
    const float4* vz = (const float4*)&swd[((ws * 3 + 1) * 4 + slot) * 512 + kb];
    const float4* vn = (const float4*)&swd[((ws * 3 + 2) * 4 + slot) * 512 + kb];
    float db_r = dbhh[gu], db_z = dbhh[HD + gu], db_n = dbhh[2 * HD + gu];
    unsigned* cnt = &g_bar_cnt[2];
    __syncthreads();

    for (int t = 0; t < TT; t++) {
        const float* hcur = g_hdec[t & 1];
        // ---- fill shh early (overlaps Phase A; separate smem region) ----
        for (int i4 = tid; i4 < BB * HD / 4; i4 += 512) {
            int b2 = i4 >> 7, k = (i4 & 127) * 4;
            *(float4*)&shh[b2 * 516 + k] = __ldcg((const float4*)&hcur[i4 * 4]);
        }
        // ---------- Phase A: flash attention partials ----------
        {
            const float* hd = hcur + ab * HD;
            float4 hreg[4];
#pragma unroll
            for (int j = 0; j < 4; j++)
                hreg[j] = __ldcg((const float4*)(hd + (j * 32 + lane) * 4));
            const float* eb = g_enhy + (size_t)ab * SS * HD;
            float m = -1e30f, l = 0.f;
            float4 cacc[4];
#pragma unroll
            for (int j = 0; j < 4; j++) cacc[j] = make_float4(0.f, 0.f, 0.f, 0.f);
            for (int s = s0 + w; s < s0 + SS / 4; s += 16) {
                const float4* e4 = (const float4*)(eb + (size_t)s * HD);
                float4 ev[4];
                float acc = 0.f;
#pragma unroll
                for (int j = 0; j < 4; j++) {
                    ev[j] = __ldg(&e4[j * 32 + lane]);
                    acc += ev[j].x * hreg[j].x + ev[j].y * hreg[j].y
                         + ev[j].z * hreg[j].z + ev[j].w * hreg[j].w;
                }
#pragma unroll
                for (int o = 16; o; o >>= 1) acc += __shfl_xor_sync(0xffffffffu, acc, o);
                float mnew = fmaxf(m, acc);
                float scale = __expf(m - mnew);
                float p = __expf(acc - mnew);
                l = l * scale + p;
#pragma unroll
                for (int j = 0; j < 4; j++) {
                    cacc[j].x = cacc[j].x * scale + p * ev[j].x;
                    cacc[j].y = cacc[j].y * scale + p * ev[j].y;
                    cacc[j].z = cacc[j].z * scale + p * ev[j].z;
                    cacc[j].w = cacc[j].w * scale + p * ev[j].w;
                }
                m = mnew;
            }
            if (lane == 0) { sm_m[w] = m; sm_l[w] = l; }
#pragma unroll
            for (int j = 0; j < 4; j++)
                ((float4*)(sm_ctx + w * HD))[j * 32 + lane] = cacc[j];
            __syncthreads();
            float M = -1e30f;
#pragma unroll
            for (int q = 0; q < 16; q++) M = fmaxf(M, sm_m[q]);
            float L = 0.f, vv = 0.f;
            int e = tid;
#pragma unroll
            for (int q = 0; q < 16; q++) {
                float f_ = __expf(sm_m[q] - M);
                L += sm_l[q] * f_;
                vv += sm_ctx[q * HD + e] * f_;
            }
            g_attc[chunk][ab][e] = vv;
            if (tid == 0) { g_attm[chunk][ab] = M; g_attl[chunk][ab] = L; }
        }
        bar_sync(cnt, (unsigned)(128 * (3 * t + 1)));
        // ---------- Phase R: distributed combine ----------
        if (tid < 128) {
            int idx = c * 128 + tid;
            int b2 = idx >> 9, e = idx & 511;
            float m0 = __ldcg(&g_attm[0][b2]), m1 = __ldcg(&g_attm[1][b2]);
            float m2 = __ldcg(&g_attm[2][b2]), m3 = __ldcg(&g_attm[3][b2]);
            float M = fmaxf(fmaxf(m0, m1), fmaxf(m2, m3));
            float f0 = __expf(m0 - M), f1 = __expf(m1 - M);
            float f2 = __expf(m2 - M), f3 = __expf(m3 - M);
            float L = __ldcg(&g_attl[0][b2]) * f0 + __ldcg(&g_attl[1][b2]) * f1
                    + __ldcg(&g_attl[2][b2]) * f2 + __ldcg(&g_attl[3][b2]) * f3;
            float v = __ldcg(&g_attc[0][b2][e]) * f0 + __ldcg(&g_attc[1][b2][e]) * f1
                    + __ldcg(&g_attc[2][b2][e]) * f2 + __ldcg(&g_attc[3][b2][e]) * f3;
            g_ctx[b2 * HD + e] = tanhf(v / L);
        }
        bar_sync(cnt, (unsigned)(128 * (3 * t + 2)));
        // ---------- Phase G: GRU step ----------
        {
            for (int i4 = tid; i4 < BB * HD / 4; i4 += 512) {
                int b2 = i4 >> 7, k = (i4 & 127) * 4;
                *(float4*)&shc[b2 * 516 + k] = __ldcg((const float4*)&g_ctx[i4 * 4]);
            }
            __syncthreads();
            const float* src = (ws ? shc : shh) + gb * 516 + kb;
            float ar = 0.f, az = 0.f, an = 0.f;
#pragma unroll 8
            for (int k4 = 0; k4 < 64; k4++) {
                float4 h4 = *(const float4*)(src + k4 * 4);
                float4 ww;
                ww = vr[k4]; ar += h4.x * ww.x + h4.y * ww.y + h4.z * ww.z + h4.w * ww.w;
                ww = vz[k4]; az += h4.x * ww.x + h4.y * ww.y + h4.z * ww.z + h4.w * ww.w;
                ww = vn[k4]; an += h4.x * ww.x + h4.y * ww.y + h4.z * ww.z + h4.w * ww.w;
            }
            int p = tid & 127;
            if (which != 0) {
                smx[((which - 1) * 3 + 0) * 132 + p] = ar;
                smx[((which - 1) * 3 + 1) * 132 + p] = az;
                smx[((which - 1) * 3 + 2) * 132 + p] = an;
            }
            __syncthreads();
            if (which == 0) {
                float ar2 = ar + smx[0 * 132 + p];
                float az2 = az + smx[1 * 132 + p];
                float an2 = an + smx[2 * 132 + p];
                float cr = smx[3 * 132 + p] + smx[6 * 132 + p];
                float cz = smx[4 * 132 + p] + smx[7 * 132 + p];
                float cn = smx[5 * 132 + p] + smx[8 * 132 + p];
                const float* gi = g_gidec + ((size_t)t * BB + gb) * (3 * HD);
                float ghr = ar2 + db_r, ghz = az2 + db_z, ghn = an2 + db_n;
                float r = 1.f / (1.f + expf(-(__ldg(&gi[gu]) + cr + ghr)));
                float z = 1.f / (1.f + expf(-(__ldg(&gi[HD + gu]) + cz + ghz)));
                float n = tanhf(__ldg(&gi[2 * HD + gu]) + cn + r * ghn);
                float hp = shh[gb * 516 + gu];
                float hn2 = (1.f - z) * n + z * hp;
                g_hdec[(t + 1) & 1][gb * HD + gu] = hn2;
                g_decout[((size_t)gb * TT + t) * HD + gu] = hn2;
            }
        }
        bar_sync(cnt, (unsigned)(128 * (3 * t + 3)));
    }
}

// ---------------- host ----------------
extern "C" void kernel_launch(void* const* d_in, const int* in_sizes, int n_in,
                              void* d_out, int out_size) {
    const int*   src_ids = (const int*)d_in[0];
    const int*   trg_ids = (const int*)d_in[1];
    const float* src_emb = (const float*)d_in[2];
    const float* trg_emb = (const float*)d_in[3];
    const float* eWihf   = (const float*)d_in[4];
    const float* eWhhf   = (const float*)d_in[5];
    const float* ebihf   = (const float*)d_in[6];
    const float* ebhhf   = (const float*)d_in[7];
    const float* eWihb   = (const float*)d_in[8];
    const float* eWhhb   = (const float*)d_in[9];
    const float* ebihb   = (const float*)d_in[10];
    const float* ebhhb   = (const float*)d_in[11];
    const float* e2dW    = (const float*)d_in[12];
    const float* e2db    = (const float*)d_in[13];
    const float* dWih    = (const float*)d_in[14];
    const float* dWhh    = (const float*)d_in[15];
    const float* dbih    = (const float*)d_in[16];
    const float* dbhh    = (const float*)d_in[17];
    const float* outW    = (const float*)d_in[18];
    const float* outb    = (const float*)d_in[19];
    float* out = (float*)d_out;

    const int ENC_SMEM = (6144 + 32 * 260) * (int)sizeof(float);   // 57856
    const int DEC_SMEM = 54724 * (int)sizeof(float);               // 218896
    cudaFuncSetAttribute(enc_persist, cudaFuncAttributeMaxDynamicSharedMemorySize, ENC_SMEM);
    cudaFuncSetAttribute(dec_persist, cudaFuncAttributeMaxDynamicSharedMemorySize, DEC_SMEM);

    float *p_srcx, *p_trgx, *p_gif, *p_gib, *p_gidec, *p_hcat, *p_hdec, *p_decout;
    cudaGetSymbolAddress((void**)&p_srcx, g_srcx);
    cudaGetSymbolAddress((void**)&p_trgx, g_trgx);
    cudaGetSymbolAddress((void**)&p_gif, g_gif);
    cudaGetSymbolAddress((void**)&p_gib, g_gib);
    cudaGetSymbolAddress((void**)&p_gidec, g_gidec);
    cudaGetSymbolAddress((void**)&p_hcat, g_hcat);
    cudaGetSymbolAddress((void**)&p_hdec, g_hdec);
    cudaGetSymbolAddress((void**)&p_decout, g_decout);

    // 1) embeddings + prep
    embed_kernel<<<(SS * BB * (EE / 4) + 255) / 256, 256>>>(src_ids, src_emb, p_srcx, SS);
    embed_kernel<<<(TT * BB * (EE / 4) + 255) / 256, 256>>>(trg_ids, trg_emb, p_trgx, TT);
    prep_kernel<<<(2 * BB * HE + 255) / 256, 256>>>();

    // 2) time-parallel input-side GRU GEMMs (tf32, K=256, 128x128 tiles)
    gemm_tf32<256><<<dim3(768 / 128, SS * BB / 128), 128>>>(p_srcx, eWihf, ebihf, p_gif, SS * BB, 768, 256);
    gemm_tf32<256><<<dim3(768 / 128, SS * BB / 128), 128>>>(p_srcx, eWihb, ebihb, p_gib, SS * BB, 768, 256);
    gemm_tf32<256><<<dim3(1536 / 128, TT * BB / 128), 128>>>(p_trgx, dWih, dbih, p_gidec, TT * BB, 1536, 768);

    // 3) persistent encoder scan (R7: 64 CTAs)
    enc_persist<<<64, 256, ENC_SMEM>>>(eWhhf, eWhhb, ebhhf, ebhhb);

    // 4) h0 = tanh([hT_f,hT_b] @ e2d_W.T + e2d_b)
    hcat_kernel<<<(BB * 2 * HE + 255) / 256, 256>>>();
    gemm_atb<<<dim3(512 / 64, 1), 256>>>(p_hcat, e2dW, e2db, p_hdec, BB, 512, 512, 512, 1);

    // 5) persistent decoder scan (3 barriers/step)
    dec_persist<<<128, 512, DEC_SMEM>>>(dWih, dWhh, dbhh);

    // 6) logits = dec_out @ out_W.T + out_b (tf32, K=512, 128x128 tiles)
    gemm_tf32<512><<<dim3(VV / 128, BB * TT / 128), 128>>>(p_decout, outW, outb, out, BB * TT, VV, 512);
}

// round 11
// speedup vs baseline: 1.0802x; 1.0802x over previous
#include <cuda_runtime.h>
#include <math.h>

#define BB 32
#define SS 400
#define TT 100
#define EE 256
#define HE 256
#define HD 512
#define VV 32000

// ---------------- scratch (device globals; no allocations) ----------------
__device__ float g_srcx[SS * BB * EE];
__device__ float g_trgx[TT * BB * EE];
__device__ float g_gif[SS * BB * 3 * HE];
__device__ float g_gib[SS * BB * 3 * HE];
__device__ float g_gidec[TT * BB * 3 * HD];
__device__ float g_enhy[BB * SS * 2 * HE];
__device__ float g_hT[2][2][HE * BB];     // [dir][parity][u*BB + b] (transposed)
__device__ float g_hcat[BB * 2 * HE];
__device__ float g_hdec[2][BB * HD];
__device__ float g_ctx[BB * HD];
__device__ float g_decout[BB * TT * HD];
__device__ float g_attm[4][BB];
__device__ float g_attl[4][BB];
__device__ float g_attc[4][BB][HD];
__device__ unsigned g_bar_cnt[4];         // 0=enc dir0, 1=enc dir1, 2=dec

// ---------------- fast transcendentals (MUFU.TANH path, sm_75+) ----------------
__device__ __forceinline__ float fast_tanh(float x) {
    float r; asm("tanh.approx.f32 %0, %1;" : "=f"(r) : "f"(x)); return r;
}
__device__ __forceinline__ float fast_sigmoid(float x) {
    return fmaf(0.5f, fast_tanh(0.5f * x), 0.5f);
}

// ---------------- cheap monotonic grid barrier (tid0-only polling) ----------------
__device__ __forceinline__ void bar_sync(unsigned* cnt, unsigned target) {
    __syncthreads();
    if (threadIdx.x == 0) {
        unsigned p;
        asm volatile("atom.release.gpu.global.add.u32 %0,[%1],%2;"
                     : "=r"(p) : "l"(cnt), "r"(1u) : "memory");
        if (p + 1u < target) {
            unsigned v;
            for (;;) {
                asm volatile("ld.acquire.gpu.global.u32 %0,[%1];" : "=r"(v) : "l"(cnt) : "memory");
                if (v >= target) break;
                __nanosleep(32);
            }
        }
    }
    __syncthreads();
}

// ---------------- embedding gather ----------------
__global__ void embed_kernel(const int* __restrict__ ids, const float* __restrict__ table,
                             float* __restrict__ out, int seq) {
    int i = blockIdx.x * blockDim.x + threadIdx.x;
    int E4 = EE / 4;
    int total = seq * BB * E4;
    if (i >= total) return;
    int e4 = i % E4;
    int sb = i / E4;
    int b = sb % BB;
    int s = sb / BB;
    int id = ids[b * seq + s];
    ((float4*)out)[i] = ((const float4*)table)[(size_t)id * E4 + e4];
}

// ---------------- prep ----------------
__global__ void prep_kernel() {
    int i = blockIdx.x * blockDim.x + threadIdx.x;
    if (i < 4) g_bar_cnt[i] = 0u;
    if (i < 2 * BB * HE) g_hT[i / (BB * HE)][0][i % (BB * HE)] = 0.f;
}

// ---------------- tf32 -> bits ----------------
__device__ __forceinline__ unsigned f2t(float x) {
    unsigned r; asm("cvt.rna.tf32.f32 %0, %1;" : "=r"(r) : "f"(x)); return r;
}

// ---------------- tf32 GEMM: 128x128 CTA tile, 4 warps, 64x64 warp tile ----------------
template<int KK>
__global__ void __launch_bounds__(128) gemm_tf32(
    const float* __restrict__ A, const float* __restrict__ Bm,
    const float* __restrict__ bias, float* __restrict__ C,
    int M, int N, int ldb)
{
    constexpr int NT = KK / 16;
    __shared__ unsigned sA[2][16][136];
    __shared__ unsigned sB[2][16][136];
    int bm = blockIdx.y * 128, bn = blockIdx.x * 128;
    int tid = threadIdx.x;            // 0..127
    int w = tid >> 5, lane = tid & 31;
    int wm = w & 1, wn = w >> 1;      // 2x2 warp grid
    int g = lane >> 2, tg = lane & 3;
    const float* Ap = A + (size_t)(bm + tid) * KK;
    const float* Bp = Bm + (size_t)(bn + tid) * ldb;

    {
        float4 va[4], vb[4];
#pragma unroll
        for (int q = 0; q < 4; q++) {
            va[q] = *(const float4*)(Ap + q * 4);
            vb[q] = *(const float4*)(Bp + q * 4);
        }
#pragma unroll
        for (int q = 0; q < 4; q++) {
            const float* pa = &va[q].x;
            const float* pb = &vb[q].x;
#pragma unroll
            for (int cc = 0; cc < 4; cc++) {
                sA[0][q * 4 + cc][tid] = f2t(pa[cc]);
                sB[0][q * 4 + cc][tid] = f2t(pb[cc]);
            }
        }
    }
    __syncthreads();

    float d[4][8][4];
#pragma unroll
    for (int f = 0; f < 4; f++)
#pragma unroll
        for (int j = 0; j < 8; j++)
#pragma unroll
            for (int e = 0; e < 4; e++) d[f][j][e] = 0.f;

    int mr0 = wm * 64 + g;
    int nc0 = wn * 64 + g;

#pragma unroll 2
    for (int i = 0; i < NT; i++) {
        const int st = i & 1;
        unsigned a[2][4][4], bf[2][8][2];
#pragma unroll
        for (int kh = 0; kh < 2; kh++) {
            int kk = kh * 8;
#pragma unroll
            for (int f = 0; f < 4; f++) {
                int mr = mr0 + f * 16;
                a[kh][f][0] = sA[st][kk + tg][mr];
                a[kh][f][1] = sA[st][kk + tg][mr + 8];
                a[kh][f][2] = sA[st][kk + tg + 4][mr];
                a[kh][f][3] = sA[st][kk + tg + 4][mr + 8];
            }
#pragma unroll
            for (int j = 0; j < 8; j++) {
                int nc = nc0 + j * 8;
                bf[kh][j][0] = sB[st][kk + tg][nc];
                bf[kh][j][1] = sB[st][kk + tg + 4][nc];
            }
        }
        float4 na[4], nb[4];
        if (i + 1 < NT) {
#pragma unroll
            for (int q = 0; q < 4; q++) {
                na[q] = *(const float4*)(Ap + (i + 1) * 16 + q * 4);
                nb[q] = *(const float4*)(Bp + (i + 1) * 16 + q * 4);
            }
        }
#pragma unroll
        for (int kh = 0; kh < 2; kh++)
#pragma unroll
            for (int f = 0; f < 4; f++)
#pragma unroll
                for (int j = 0; j < 8; j++)
                    asm volatile(
                        "mma.sync.aligned.m16n8k8.row.col.f32.tf32.tf32.f32 "
                        "{%0,%1,%2,%3}, {%4,%5,%6,%7}, {%8,%9}, {%0,%1,%2,%3};"
                        : "+f"(d[f][j][0]), "+f"(d[f][j][1]),
                          "+f"(d[f][j][2]), "+f"(d[f][j][3])
                        : "r"(a[kh][f][0]), "r"(a[kh][f][1]), "r"(a[kh][f][2]), "r"(a[kh][f][3]),
                          "r"(bf[kh][j][0]), "r"(bf[kh][j][1]));
        if (i + 1 < NT) {
            const int ns = st ^ 1;
#pragma unroll
            for (int q = 0; q < 4; q++) {
                const float* pa = &na[q].x;
                const float* pb = &nb[q].x;
#pragma unroll
                for (int cc = 0; cc < 4; cc++) {
                    sA[ns][q * 4 + cc][tid] = f2t(pa[cc]);
                    sB[ns][q * 4 + cc][tid] = f2t(pb[cc]);
                }
            }
        }
        __syncthreads();
    }
#pragma unroll
    for (int f = 0; f < 4; f++) {
        int r0 = bm + wm * 64 + f * 16 + g;
#pragma unroll
        for (int j = 0; j < 8; j++) {
            int col = bn + wn * 64 + j * 8 + tg * 2;
            float b0 = __ldg(&bias[col]), b1 = __ldg(&bias[col + 1]);
            float2 v0 = make_float2(d[f][j][0] + b0, d[f][j][1] + b1);
            float2 v1 = make_float2(d[f][j][2] + b0, d[f][j][3] + b1);
            *(float2*)&C[(size_t)r0 * N + col] = v0;
            *(float2*)&C[(size_t)(r0 + 8) * N + col] = v1;
        }
    }
}

// ---------------- small fp32 GEMM (e2d only, M=32, tanh) ----------------
__global__ void __launch_bounds__(256) gemm_atb(
    const float* __restrict__ A, const float* __restrict__ Bm,
    const float* __restrict__ bias, float* __restrict__ C,
    int M, int N, int K, int ldb, int act)
{
    __shared__ float sA[16][68];
    __shared__ float sB[16][68];
    int bm = blockIdx.y * 64, bn = blockIdx.x * 64;
    int tid = threadIdx.x;
    int tm = (tid >> 4) << 2, tn = (tid & 15) << 2;
    int lr = tid >> 2, lc = (tid & 3) << 2;
    float acc[4][4] = {};
    for (int k0 = 0; k0 < K; k0 += 16) {
        float4 a4 = make_float4(0.f, 0.f, 0.f, 0.f);
        if (bm + lr < M) a4 = *(const float4*)&A[(size_t)(bm + lr) * K + k0 + lc];
        sA[lc + 0][lr] = a4.x; sA[lc + 1][lr] = a4.y; sA[lc + 2][lr] = a4.z; sA[lc + 3][lr] = a4.w;
        float4 b4 = *(const float4*)&Bm[(size_t)(bn + lr) * ldb + k0 + lc];
        sB[lc + 0][lr] = b4.x; sB[lc + 1][lr] = b4.y; sB[lc + 2][lr] = b4.z; sB[lc + 3][lr] = b4.w;
        __syncthreads();
#pragma unroll
        for (int kk = 0; kk < 16; kk++) {
            float4 av = *(const float4*)&sA[kk][tm];
            float4 bv = *(const float4*)&sB[kk][tn];
            float a[4] = {av.x, av.y, av.z, av.w};
            float b[4] = {bv.x, bv.y, bv.z, bv.w};
#pragma unroll
            for (int i = 0; i < 4; i++)
#pragma unroll
                for (int j = 0; j < 4; j++) acc[i][j] += a[i] * b[j];
        }
        __syncthreads();
    }
#pragma unroll
    for (int i = 0; i < 4; i++) {
        int row = bm + tm + i;
        if (row >= M) continue;
        float4 v;
        float* pv = &v.x;
#pragma unroll
        for (int j = 0; j < 4; j++) {
            float x = acc[i][j] + bias[bn + tn + j];
            if (act == 1) x = tanhf(x);
            pv[j] = x;
        }
        *(float4*)&C[(size_t)row * N + bn + tn] = v;
    }
}

// ---------------- persistent encoder: 64 CTAs x 256 thr ----------------
__global__ void __launch_bounds__(256) enc_persist(
    const float* __restrict__ Whh_f, const float* __restrict__ Whh_b,
    const float* __restrict__ bhh_f, const float* __restrict__ bhh_b)
{
    extern __shared__ float es[];
    float* swt = es;            // [3*8*256]
    float* sh  = es + 6144;     // [32][260]
    int c = blockIdx.x;
    int dir = c >> 5;
    int ublk = c & 31;
    int tid = threadIdx.x;
    int b = tid & 31;
    int ul = tid >> 5;
    int u = ublk * 8 + ul;
    const float* Whh = dir ? Whh_b : Whh_f;
    const float* bhh = dir ? bhh_b : bhh_f;
    const float* gibase = dir ? g_gib : g_gif;
    for (int i = tid; i < 6144; i += 256) {
        int gate = i >> 11;
        int rem = i & 2047;
        swt[i] = Whh[((size_t)gate * HE + ublk * 8 + (rem >> 8)) * HE + (rem & 255)];
    }
    float br_ = bhh[u], bz_ = bhh[HE + u], bn_ = bhh[2 * HE + u];
    const float4* wr = (const float4*)&swt[(0 * 8 + ul) * 256];
    const float4* wz = (const float4*)&swt[(1 * 8 + ul) * 256];
    const float4* wn = (const float4*)&swt[(2 * 8 + ul) * 256];
    unsigned* cnt = &g_bar_cnt[dir];
    const float* hb = sh + b * 260;

    for (int t = 0; t < SS; t++) {
        if (t > 0) bar_sync(cnt, (unsigned)(32 * t));
        const float* hsrc = g_hT[dir][t & 1];
        for (int i = tid; i < BB * HE; i += 256)
            sh[(i & 31) * 260 + (i >> 5)] = __ldcg(&hsrc[i]);
        __syncthreads();
        float ar = 0.f, az = 0.f, an = 0.f;
#pragma unroll 8
        for (int k4 = 0; k4 < 64; k4++) {
            float4 h4 = *(const float4*)(hb + k4 * 4);
            float4 ww;
            ww = wr[k4]; ar += h4.x * ww.x + h4.y * ww.y + h4.z * ww.z + h4.w * ww.w;
            ww = wz[k4]; az += h4.x * ww.x + h4.y * ww.y + h4.z * ww.z + h4.w * ww.w;
            ww = wn[k4]; an += h4.x * ww.x + h4.y * ww.y + h4.z * ww.z + h4.w * ww.w;
        }
        int s = dir ? (SS - 1 - t) : t;
        const float* gi = gibase + (size_t)(s * BB + b) * (3 * HE);
        float ghr = ar + br_, ghz = az + bz_, ghn = an + bn_;
        float r = fast_sigmoid(__ldg(&gi[u]) + ghr);
        float z = fast_sigmoid(__ldg(&gi[HE + u]) + ghz);
        float n = fast_tanh(__ldg(&gi[2 * HE + u]) + r * ghn);
        float hp = hb[u];
        float hn2 = (1.f - z) * n + z * hp;
        g_hT[dir][(t + 1) & 1][u * BB + b] = hn2;
        g_enhy[((size_t)b * SS + s) * (2 * HE) + dir * HE + u] = hn2;
        __syncthreads();
    }
}

// ---------------- build [hT_f, hT_b] ----------------
__global__ void hcat_kernel() {
    int i = blockIdx.x * blockDim.x + threadIdx.x;
    if (i >= BB * 2 * HE) return;
    int b = i >> 9;
    int j = i & 511;
    float v;
    if (j < HE) v = g_enhy[((size_t)b * SS + (SS - 1)) * (2 * HE) + j];
    else        v = g_enhy[((size_t)b * SS + 0) * (2 * HE) + j];
    g_hcat[i] = v;
}

// ---------------- persistent decoder: 128 CTAs x 512 thr ----------------
__global__ void __launch_bounds__(512) dec_persist(
    const float* __restrict__ dWih, const float* __restrict__ dWhh,
    const float* __restrict__ dbhh)
{
    extern __shared__ float sm[];
    float* swd    = sm;                 // [12288]
    float* shh    = sm + 12288;         // [32][516]
    float* shc    = sm + 28800;         // [32][516]
    float* smx    = sm + 45312;         // [9*132]
    float* sm_m   = sm + 46500;         // [16]
    float* sm_l   = sm + 46516;         // [16]
    float* sm_ctx = sm + 46532;         // [16*512]  total 54724 floats

    int c = blockIdx.x;
    int tid = threadIdx.x;
    int lane = tid & 31, w = tid >> 5;
    int ab = c & 31, chunk = c >> 5, s0 = chunk * (SS / 4);
    int gb = tid & 31;
    int slot = (tid >> 5) & 3;
    int which = tid >> 7;
    int gu = c * 4 + slot;

    for (int i = tid; i < 12288; i += 512) {
        int sg = i >> 11;
        int rem = i & 2047;
        int sl = rem >> 9;
        int k = rem & 511;
        int s_ = sg / 3, g2 = sg % 3;
        int uu = c * 4 + sl;
        swd[i] = (s_ == 0) ? dWhh[((size_t)g2 * HD + uu) * HD + k]
                           : dWih[((size_t)(g2 * HD + uu)) * 768 + 256 + k];
    }
    int ws = which >> 1;
    int kb = (which & 1) * 256;
    const float4* vr = (const float4*)&swd[((ws * 3 + 0) * 4 + slot) * 512 + kb];
    const float4* vz = (const float4*)&swd[((ws * 3 + 1) * 4 + slot) * 512 + kb];
    const float4* vn = (const float4*)&swd[((ws * 3 + 2) * 4 + slot) * 512 + kb];
    float db_r = dbhh[gu], db_z = dbhh[HD + gu], db_n = dbhh[2 * HD + gu];
    unsigned* cnt = &g_bar_cnt[2];
    __syncthreads();

    for (int t = 0; t < TT; t++) {
        const float* hcur = g_hdec[t & 1];
        // ---- fill shh early (overlaps Phase A; separate smem region) ----
        for (int i4 = tid; i4 < BB * HD / 4; i4 += 512) {
            int b2 = i4 >> 7, k = (i4 & 127) * 4;
            *(float4*)&shh[b2 * 516 + k] = __ldcg((const float4*)&hcur[i4 * 4]);
        }
        // ---------- Phase A: flash attention partials ----------
        {
            const float* hd = hcur + ab * HD;
            float4 hreg[4];
#pragma unroll
            for (int j = 0; j < 4; j++)
                hreg[j] = __ldcg((const float4*)(hd + (j * 32 + lane) * 4));
            const float* eb = g_enhy + (size_t)ab * SS * HD;
            float m = -1e30f, l = 0.f;
            float4 cacc[4];
#pragma unroll
            for (int j = 0; j < 4; j++) cacc[j] = make_float4(0.f, 0.f, 0.f, 0.f);
            for (int s = s0 + w; s < s0 + SS / 4; s += 16) {
                const float4* e4 = (const float4*)(eb + (size_t)s * HD);
                float4 ev[4];
                float acc = 0.f;
#pragma unroll
                for (int j = 0; j < 4; j++) {
                    ev[j] = __ldg(&e4[j * 32 + lane]);
                    acc += ev[j].x * hreg[j].x + ev[j].y * hreg[j].y
                         + ev[j].z * hreg[j].z + ev[j].w * hreg[j].w;
                }
#pragma unroll
                for (int o = 16; o; o >>= 1) acc += __shfl_xor_sync(0xffffffffu, acc, o);
                float mnew = fmaxf(m, acc);
                float scale = __expf(m - mnew);
                float p = __expf(acc - mnew);
                l = l * scale + p;
#pragma unroll
                for (int j = 0; j < 4; j++) {
                    cacc[j].x = cacc[j].x * scale + p * ev[j].x;
                    cacc[j].y = cacc[j].y * scale + p * ev[j].y;
                    cacc[j].z = cacc[j].z * scale + p * ev[j].z;
                    cacc[j].w = cacc[j].w * scale + p * ev[j].w;
                }
                m = mnew;
            }
            if (lane == 0) { sm_m[w] = m; sm_l[w] = l; }
#pragma unroll
            for (int j = 0; j < 4; j++)
                ((float4*)(sm_ctx + w * HD))[j * 32 + lane] = cacc[j];
            __syncthreads();
            float M = -1e30f;
#pragma unroll
            for (int q = 0; q < 16; q++) M = fmaxf(M, sm_m[q]);
            float L = 0.f, vv = 0.f;
            int e = tid;
#pragma unroll
            for (int q = 0; q < 16; q++) {
                float f_ = __expf(sm_m[q] - M);
                L += sm_l[q] * f_;
                vv += sm_ctx[q * HD + e] * f_;
            }
            g_attc[chunk][ab][e] = vv;
            if (tid == 0) { g_attm[chunk][ab] = M; g_attl[chunk][ab] = L; }
        }
        bar_sync(cnt, (unsigned)(128 * (3 * t + 1)));
        // ---------- Phase R: distributed combine ----------
        if (tid < 128) {
            int idx = c * 128 + tid;
            int b2 = idx >> 9, e = idx & 511;
            float m0 = __ldcg(&g_attm[0][b2]), m1 = __ldcg(&g_attm[1][b2]);
            float m2 = __ldcg(&g_attm[2][b2]), m3 = __ldcg(&g_attm[3][b2]);
            float M = fmaxf(fmaxf(m0, m1), fmaxf(m2, m3));
            float f0 = __expf(m0 - M), f1 = __expf(m1 - M);
            float f2 = __expf(m2 - M), f3 = __expf(m3 - M);
            float L = __ldcg(&g_attl[0][b2]) * f0 + __ldcg(&g_attl[1][b2]) * f1
                    + __ldcg(&g_attl[2][b2]) * f2 + __ldcg(&g_attl[3][b2]) * f3;
            float v = __ldcg(&g_attc[0][b2][e]) * f0 + __ldcg(&g_attc[1][b2][e]) * f1
                    + __ldcg(&g_attc[2][b2][e]) * f2 + __ldcg(&g_attc[3][b2][e]) * f3;
            g_ctx[b2 * HD + e] = fast_tanh(__fdividef(v, L));
        }
        bar_sync(cnt, (unsigned)(128 * (3 * t + 2)));
        // ---------- Phase G: GRU step ----------
        {
            for (int i4 = tid; i4 < BB * HD / 4; i4 += 512) {
                int b2 = i4 >> 7, k = (i4 & 127) * 4;
                *(float4*)&shc[b2 * 516 + k] = __ldcg((const float4*)&g_ctx[i4 * 4]);
            }
            __syncthreads();
            const float* src = (ws ? shc : shh) + gb * 516 + kb;
            float ar = 0.f, az = 0.f, an = 0.f;
#pragma unroll 8
            for (int k4 = 0; k4 < 64; k4++) {
                float4 h4 = *(const float4*)(src + k4 * 4);
                float4 ww;
                ww = vr[k4]; ar += h4.x * ww.x + h4.y * ww.y + h4.z * ww.z + h4.w * ww.w;
                ww = vz[k4]; az += h4.x * ww.x + h4.y * ww.y + h4.z * ww.z + h4.w * ww.w;
                ww = vn[k4]; an += h4.x * ww.x + h4.y * ww.y + h4.z * ww.z + h4.w * ww.w;
            }
            int p = tid & 127;
            if (which != 0) {
                smx[((which - 1) * 3 + 0) * 132 + p] = ar;
                smx[((which - 1) * 3 + 1) * 132 + p] = az;
                smx[((which - 1) * 3 + 2) * 132 + p] = an;
            }
            __syncthreads();
            if (which == 0) {
                float ar2 = ar + smx[0 * 132 + p];
                float az2 = az + smx[1 * 132 + p];
                float an2 = an + smx[2 * 132 + p];
                float cr = smx[3 * 132 + p] + smx[6 * 132 + p];
                float cz = smx[4 * 132 + p] + smx[7 * 132 + p];
                float cn = smx[5 * 132 + p] + smx[8 * 132 + p];
                const float* gi = g_gidec + ((size_t)t * BB + gb) * (3 * HD);
                float ghr = ar2 + db_r, ghz = az2 + db_z, ghn = an2 + db_n;
                float r = fast_sigmoid(__ldg(&gi[gu]) + cr + ghr);
                float z = fast_sigmoid(__ldg(&gi[HD + gu]) + cz + ghz);
                float n = fast_tanh(__ldg(&gi[2 * HD + gu]) + cn + r * ghn);
                float hp = shh[gb * 516 + gu];
                float hn2 = (1.f - z) * n + z * hp;
                g_hdec[(t + 1) & 1][gb * HD + gu] = hn2;
                g_decout[((size_t)gb * TT + t) * HD + gu] = hn2;
            }
        }
        bar_sync(cnt, (unsigned)(128 * (3 * t + 3)));
    }
}

// ---------------- host ----------------
extern "C" void kernel_launch(void* const* d_in, const int* in_sizes, int n_in,
                              void* d_out, int out_size) {
    const int*   src_ids = (const int*)d_in[0];
    const int*   trg_ids = (const int*)d_in[1];
    const float* src_emb = (const float*)d_in[2];
    const float* trg_emb = (const float*)d_in[3];
    const float* eWihf   = (const float*)d_in[4];
    const float* eWhhf   = (const float*)d_in[5];
    const float* ebihf   = (const float*)d_in[6];
    const float* ebhhf   = (const float*)d_in[7];
    const float* eWihb   = (const float*)d_in[8];
    const float* eWhhb   = (const float*)d_in[9];
    const float* ebihb   = (const float*)d_in[10];
    const float* ebhhb   = (const float*)d_in[11];
    const float* e2dW    = (const float*)d_in[12];
    const float* e2db    = (const float*)d_in[13];
    const float* dWih    = (const float*)d_in[14];
    const float* dWhh    = (const float*)d_in[15];
    const float* dbih    = (const float*)d_in[16];
    const float* dbhh    = (const float*)d_in[17];
    const float* outW    = (const float*)d_in[18];
    const float* outb    = (const float*)d_in[19];
    float* out = (float*)d_out;

    const int ENC_SMEM = (6144 + 32 * 260) * (int)sizeof(float);   // 57856
    const int DEC_SMEM = 54724 * (int)sizeof(float);               // 218896
    cudaFuncSetAttribute(enc_persist, cudaFuncAttributeMaxDynamicSharedMemorySize, ENC_SMEM);
    cudaFuncSetAttribute(dec_persist, cudaFuncAttributeMaxDynamicSharedMemorySize, DEC_SMEM);

    float *p_srcx, *p_trgx, *p_gif, *p_gib, *p_gidec, *p_hcat, *p_hdec, *p_decout;
    cudaGetSymbolAddress((void**)&p_srcx, g_srcx);
    cudaGetSymbolAddress((void**)&p_trgx, g_trgx);
    cudaGetSymbolAddress((void**)&p_gif, g_gif);
    cudaGetSymbolAddress((void**)&p_gib, g_gib);
    cudaGetSymbolAddress((void**)&p_gidec, g_gidec);
    cudaGetSymbolAddress((void**)&p_hcat, g_hcat);
    cudaGetSymbolAddress((void**)&p_hdec, g_hdec);
    cudaGetSymbolAddress((void**)&p_decout, g_decout);

    // 1) embeddings + prep
    embed_kernel<<<(SS * BB * (EE / 4) + 255) / 256, 256>>>(src_ids, src_emb, p_srcx, SS);
    embed_kernel<<<(TT * BB * (EE / 4) + 255) / 256, 256>>>(trg_ids, trg_emb, p_trgx, TT);
    prep_kernel<<<(2 * BB * HE + 255) / 256, 256>>>();

    // 2) time-parallel input-side GRU GEMMs (tf32, K=256, 128x128 tiles)
    gemm_tf32<256><<<dim3(768 / 128, SS * BB / 128), 128>>>(p_srcx, eWihf, ebihf, p_gif, SS * BB, 768, 256);
    gemm_tf32<256><<<dim3(768 / 128, SS * BB / 128), 128>>>(p_srcx, eWihb, ebihb, p_gib, SS * BB, 768, 256);
    gemm_tf32<256><<<dim3(1536 / 128, TT * BB / 128), 128>>>(p_trgx, dWih, dbih, p_gidec, TT * BB, 1536, 768);

    // 3) persistent encoder scan (64 CTAs)
    enc_persist<<<64, 256, ENC_SMEM>>>(eWhhf, eWhhb, ebhhf, ebhhb);

    // 4) h0 = tanh([hT_f,hT_b] @ e2d_W.T + e2d_b)
    hcat_kernel<<<(BB * 2 * HE + 255) / 256, 256>>>();
    gemm_atb<<<dim3(512 / 64, 1), 256>>>(p_hcat, e2dW, e2db, p_hdec, BB, 512, 512, 512, 1);

    // 5) persistent decoder scan (3 barriers/step)
    dec_persist<<<128, 512, DEC_SMEM>>>(dWih, dWhh, dbhh);

    // 6) logits = dec_out @ out_W.T + out_b (tf32, K=512, 128x128 tiles)
    gemm_tf32<512><<<dim3(VV / 128, BB * TT / 128), 128>>>(p_decout, outW, outb, out, BB * TT, VV, 512);
}

// round 12
// speedup vs baseline: 1.0859x; 1.0053x over previous
#include <cuda_runtime.h>
#include <math.h>

#define BB 32
#define SS 400
#define TT 100
#define EE 256
#define HE 256
#define HD 512
#define VV 32000

// smem row strides: mod 32 == 12 -> conflict-free LDS.128 across lanes-vary-row
#define EST 268
#define DST 524

// ---------------- scratch (device globals; no allocations) ----------------
__device__ float g_srcx[SS * BB * EE];
__device__ float g_trgx[TT * BB * EE];
__device__ float g_gif[SS * BB * 3 * HE];
__device__ float g_gib[SS * BB * 3 * HE];
__device__ float g_gidec[TT * BB * 3 * HD];
__device__ float g_enhy[BB * SS * 2 * HE];
__device__ float g_hT[2][2][HE * BB];     // [dir][parity][u*BB + b] (transposed)
__device__ float g_hcat[BB * 2 * HE];
__device__ float g_hdec[2][BB * HD];
__device__ float g_ctx[BB * HD];
__device__ float g_decout[BB * TT * HD];
__device__ float g_attm[4][BB];
__device__ float g_attl[4][BB];
__device__ float g_attc[4][BB][HD];
__device__ unsigned g_bar_cnt[4];         // 0=enc dir0, 1=enc dir1, 2=dec

// ---------------- fast transcendentals (MUFU.TANH path, sm_75+) ----------------
__device__ __forceinline__ float fast_tanh(float x) {
    float r; asm("tanh.approx.f32 %0, %1;" : "=f"(r) : "f"(x)); return r;
}
__device__ __forceinline__ float fast_sigmoid(float x) {
    return fmaf(0.5f, fast_tanh(0.5f * x), 0.5f);
}

// ---------------- cheap monotonic grid barrier (tid0-only polling) ----------------
__device__ __forceinline__ void bar_sync(unsigned* cnt, unsigned target) {
    __syncthreads();
    if (threadIdx.x == 0) {
        unsigned p;
        asm volatile("atom.release.gpu.global.add.u32 %0,[%1],%2;"
                     : "=r"(p) : "l"(cnt), "r"(1u) : "memory");
        if (p + 1u < target) {
            unsigned v;
            for (;;) {
                asm volatile("ld.acquire.gpu.global.u32 %0,[%1];" : "=r"(v) : "l"(cnt) : "memory");
                if (v >= target) break;
                __nanosleep(32);
            }
        }
    }
    __syncthreads();
}

// ---------------- embedding gather ----------------
__global__ void embed_kernel(const int* __restrict__ ids, const float* __restrict__ table,
                             float* __restrict__ out, int seq) {
    int i = blockIdx.x * blockDim.x + threadIdx.x;
    int E4 = EE / 4;
    int total = seq * BB * E4;
    if (i >= total) return;
    int e4 = i % E4;
    int sb = i / E4;
    int b = sb % BB;
    int s = sb / BB;
    int id = ids[b * seq + s];
    ((float4*)out)[i] = ((const float4*)table)[(size_t)id * E4 + e4];
}

// ---------------- prep ----------------
__global__ void prep_kernel() {
    int i = blockIdx.x * blockDim.x + threadIdx.x;
    if (i < 4) g_bar_cnt[i] = 0u;
    if (i < 2 * BB * HE) g_hT[i / (BB * HE)][0][i % (BB * HE)] = 0.f;
}

// ---------------- tf32 -> bits ----------------
__device__ __forceinline__ unsigned f2t(float x) {
    unsigned r; asm("cvt.rna.tf32.f32 %0, %1;" : "=r"(r) : "f"(x)); return r;
}

// ---------------- tf32 GEMM: 128x128 CTA tile, 4 warps, 64x64 warp tile ----------------
template<int KK>
__global__ void __launch_bounds__(128) gemm_tf32(
    const float* __restrict__ A, const float* __restrict__ Bm,
    const float* __restrict__ bias, float* __restrict__ C,
    int M, int N, int ldb)
{
    constexpr int NT = KK / 16;
    __shared__ unsigned sA[2][16][136];
    __shared__ unsigned sB[2][16][136];
    int bm = blockIdx.y * 128, bn = blockIdx.x * 128;
    int tid = threadIdx.x;            // 0..127
    int w = tid >> 5, lane = tid & 31;
    int wm = w & 1, wn = w >> 1;      // 2x2 warp grid
    int g = lane >> 2, tg = lane & 3;
    const float* Ap = A + (size_t)(bm + tid) * KK;
    const float* Bp = Bm + (size_t)(bn + tid) * ldb;

    {
        float4 va[4], vb[4];
#pragma unroll
        for (int q = 0; q < 4; q++) {
            va[q] = *(const float4*)(Ap + q * 4);
            vb[q] = *(const float4*)(Bp + q * 4);
        }
#pragma unroll
        for (int q = 0; q < 4; q++) {
            const float* pa = &va[q].x;
            const float* pb = &vb[q].x;
#pragma unroll
            for (int cc = 0; cc < 4; cc++) {
                sA[0][q * 4 + cc][tid] = f2t(pa[cc]);
                sB[0][q * 4 + cc][tid] = f2t(pb[cc]);
            }
        }
    }
    __syncthreads();

    float d[4][8][4];
#pragma unroll
    for (int f = 0; f < 4; f++)
#pragma unroll
        for (int j = 0; j < 8; j++)
#pragma unroll
            for (int e = 0; e < 4; e++) d[f][j][e] = 0.f;

    int mr0 = wm * 64 + g;
    int nc0 = wn * 64 + g;

#pragma unroll 2
    for (int i = 0; i < NT; i++) {
        const int st = i & 1;
        unsigned a[2][4][4], bf[2][8][2];
#pragma unroll
        for (int kh = 0; kh < 2; kh++) {
            int kk = kh * 8;
#pragma unroll
            for (int f = 0; f < 4; f++) {
                int mr = mr0 + f * 16;
                a[kh][f][0] = sA[st][kk + tg][mr];
                a[kh][f][1] = sA[st][kk + tg][mr + 8];
                a[kh][f][2] = sA[st][kk + tg + 4][mr];
                a[kh][f][3] = sA[st][kk + tg + 4][mr + 8];
            }
#pragma unroll
            for (int j = 0; j < 8; j++) {
                int nc = nc0 + j * 8;
                bf[kh][j][0] = sB[st][kk + tg][nc];
                bf[kh][j][1] = sB[st][kk + tg + 4][nc];
            }
        }
        float4 na[4], nb[4];
        if (i + 1 < NT) {
#pragma unroll
            for (int q = 0; q < 4; q++) {
                na[q] = *(const float4*)(Ap + (i + 1) * 16 + q * 4);
                nb[q] = *(const float4*)(Bp + (i + 1) * 16 + q * 4);
            }
        }
#pragma unroll
        for (int kh = 0; kh < 2; kh++)
#pragma unroll
            for (int f = 0; f < 4; f++)
#pragma unroll
                for (int j = 0; j < 8; j++)
                    asm volatile(
                        "mma.sync.aligned.m16n8k8.row.col.f32.tf32.tf32.f32 "
                        "{%0,%1,%2,%3}, {%4,%5,%6,%7}, {%8,%9}, {%0,%1,%2,%3};"
                        : "+f"(d[f][j][0]), "+f"(d[f][j][1]),
                          "+f"(d[f][j][2]), "+f"(d[f][j][3])
                        : "r"(a[kh][f][0]), "r"(a[kh][f][1]), "r"(a[kh][f][2]), "r"(a[kh][f][3]),
                          "r"(bf[kh][j][0]), "r"(bf[kh][j][1]));
        if (i + 1 < NT) {
            const int ns = st ^ 1;
#pragma unroll
            for (int q = 0; q < 4; q++) {
                const float* pa = &na[q].x;
                const float* pb = &nb[q].x;
#pragma unroll
                for (int cc = 0; cc < 4; cc++) {
                    sA[ns][q * 4 + cc][tid] = f2t(pa[cc]);
                    sB[ns][q * 4 + cc][tid] = f2t(pb[cc]);
                }
            }
        }
        __syncthreads();
    }
#pragma unroll
    for (int f = 0; f < 4; f++) {
        int r0 = bm + wm * 64 + f * 16 + g;
#pragma unroll
        for (int j = 0; j < 8; j++) {
            int col = bn + wn * 64 + j * 8 + tg * 2;
            float b0 = __ldg(&bias[col]), b1 = __ldg(&bias[col + 1]);
            float2 v0 = make_float2(d[f][j][0] + b0, d[f][j][1] + b1);
            float2 v1 = make_float2(d[f][j][2] + b0, d[f][j][3] + b1);
            *(float2*)&C[(size_t)r0 * N + col] = v0;
            *(float2*)&C[(size_t)(r0 + 8) * N + col] = v1;
        }
    }
}

// ---------------- small fp32 GEMM (e2d only, M=32, tanh) ----------------
__global__ void __launch_bounds__(256) gemm_atb(
    const float* __restrict__ A, const float* __restrict__ Bm,
    const float* __restrict__ bias, float* __restrict__ C,
    int M, int N, int K, int ldb, int act)
{
    __shared__ float sA[16][68];
    __shared__ float sB[16][68];
    int bm = blockIdx.y * 64, bn = blockIdx.x * 64;
    int tid = threadIdx.x;
    int tm = (tid >> 4) << 2, tn = (tid & 15) << 2;
    int lr = tid >> 2, lc = (tid & 3) << 2;
    float acc[4][4] = {};
    for (int k0 = 0; k0 < K; k0 += 16) {
        float4 a4 = make_float4(0.f, 0.f, 0.f, 0.f);
        if (bm + lr < M) a4 = *(const float4*)&A[(size_t)(bm + lr) * K + k0 + lc];
        sA[lc + 0][lr] = a4.x; sA[lc + 1][lr] = a4.y; sA[lc + 2][lr] = a4.z; sA[lc + 3][lr] = a4.w;
        float4 b4 = *(const float4*)&Bm[(size_t)(bn + lr) * ldb + k0 + lc];
        sB[lc + 0][lr] = b4.x; sB[lc + 1][lr] = b4.y; sB[lc + 2][lr] = b4.z; sB[lc + 3][lr] = b4.w;
        __syncthreads();
#pragma unroll
        for (int kk = 0; kk < 16; kk++) {
            float4 av = *(const float4*)&sA[kk][tm];
            float4 bv = *(const float4*)&sB[kk][tn];
            float a[4] = {av.x, av.y, av.z, av.w};
            float b[4] = {bv.x, bv.y, bv.z, bv.w};
#pragma unroll
            for (int i = 0; i < 4; i++)
#pragma unroll
                for (int j = 0; j < 4; j++) acc[i][j] += a[i] * b[j];
        }
        __syncthreads();
    }
#pragma unroll
    for (int i = 0; i < 4; i++) {
        int row = bm + tm + i;
        if (row >= M) continue;
        float4 v;
        float* pv = &v.x;
#pragma unroll
        for (int j = 0; j < 4; j++) {
            float x = acc[i][j] + bias[bn + tn + j];
            if (act == 1) x = tanhf(x);
            pv[j] = x;
        }
        *(float4*)&C[(size_t)row * N + bn + tn] = v;
    }
}

// ---------------- persistent encoder: 64 CTAs x 256 thr ----------------
__global__ void __launch_bounds__(256) enc_persist(
    const float* __restrict__ Whh_f, const float* __restrict__ Whh_b,
    const float* __restrict__ bhh_f, const float* __restrict__ bhh_b)
{
    extern __shared__ float es[];
    float* swt = es;            // [3*8*256]
    float* sh  = es + 6144;     // [32][EST]
    int c = blockIdx.x;
    int dir = c >> 5;
    int ublk = c & 31;
    int tid = threadIdx.x;
    int b = tid & 31;
    int ul = tid >> 5;
    int u = ublk * 8 + ul;
    const float* Whh = dir ? Whh_b : Whh_f;
    const float* bhh = dir ? bhh_b : bhh_f;
    const float* gibase = dir ? g_gib : g_gif;
    for (int i = tid; i < 6144; i += 256) {
        int gate = i >> 11;
        int rem = i & 2047;
        swt[i] = Whh[((size_t)gate * HE + ublk * 8 + (rem >> 8)) * HE + (rem & 255)];
    }
    float br_ = bhh[u], bz_ = bhh[HE + u], bn_ = bhh[2 * HE + u];
    const float4* wr = (const float4*)&swt[(0 * 8 + ul) * 256];
    const float4* wz = (const float4*)&swt[(1 * 8 + ul) * 256];
    const float4* wn = (const float4*)&swt[(2 * 8 + ul) * 256];
    unsigned* cnt = &g_bar_cnt[dir];
    const float* hb = sh + b * EST;

    for (int t = 0; t < SS; t++) {
        if (t > 0) bar_sync(cnt, (unsigned)(32 * t));
        const float* hsrc = g_hT[dir][t & 1];
        for (int i = tid; i < BB * HE; i += 256)
            sh[(i & 31) * EST + (i >> 5)] = __ldcg(&hsrc[i]);
        __syncthreads();
        float ar = 0.f, az = 0.f, an = 0.f;
#pragma unroll 8
        for (int k4 = 0; k4 < 64; k4++) {
            float4 h4 = *(const float4*)(hb + k4 * 4);
            float4 ww;
            ww = wr[k4]; ar += h4.x * ww.x + h4.y * ww.y + h4.z * ww.z + h4.w * ww.w;
            ww = wz[k4]; az += h4.x * ww.x + h4.y * ww.y + h4.z * ww.z + h4.w * ww.w;
            ww = wn[k4]; an += h4.x * ww.x + h4.y * ww.y + h4.z * ww.z + h4.w * ww.w;
        }
        int s = dir ? (SS - 1 - t) : t;
        const float* gi = gibase + (size_t)(s * BB + b) * (3 * HE);
        float ghr = ar + br_, ghz = az + bz_, ghn = an + bn_;
        float r = fast_sigmoid(__ldg(&gi[u]) + ghr);
        float z = fast_sigmoid(__ldg(&gi[HE + u]) + ghz);
        float n = fast_tanh(__ldg(&gi[2 * HE + u]) + r * ghn);
        float hp = hb[u];
        float hn2 = (1.f - z) * n + z * hp;
        g_hT[dir][(t + 1) & 1][u * BB + b] = hn2;
        g_enhy[((size_t)b * SS + s) * (2 * HE) + dir * HE + u] = hn2;
        __syncthreads();
    }
}

// ---------------- build [hT_f, hT_b] ----------------
__global__ void hcat_kernel() {
    int i = blockIdx.x * blockDim.x + threadIdx.x;
    if (i >= BB * 2 * HE) return;
    int b = i >> 9;
    int j = i & 511;
    float v;
    if (j < HE) v = g_enhy[((size_t)b * SS + (SS - 1)) * (2 * HE) + j];
    else        v = g_enhy[((size_t)b * SS + 0) * (2 * HE) + j];
    g_hcat[i] = v;
}

// ---------------- persistent decoder: 128 CTAs x 512 thr ----------------
__global__ void __launch_bounds__(512) dec_persist(
    const float* __restrict__ dWih, const float* __restrict__ dWhh,
    const float* __restrict__ dbhh)
{
    extern __shared__ float sm[];
    float* swd    = sm;                       // [12288]
    float* shh    = sm + 12288;               // [32][DST]
    float* shc    = sm + 12288 + 32 * DST;    // [32][DST]
    float* smx    = sm + 12288 + 64 * DST;            // [9*132]
    float* sm_m   = sm + 12288 + 64 * DST + 1188;     // [16]
    float* sm_l   = sm_m + 16;                        // [16]
    float* sm_ctx = sm_l + 16;                        // [16*512]

    int c = blockIdx.x;
    int tid = threadIdx.x;
    int lane = tid & 31, w = tid >> 5;
    int ab = c & 31, chunk = c >> 5, s0 = chunk * (SS / 4);
    int gb = tid & 31;
    int slot = (tid >> 5) & 3;
    int which = tid >> 7;
    int gu = c * 4 + slot;

    for (int i = tid; i < 12288; i += 512) {
        int sg = i >> 11;
        int rem = i & 2047;
        int sl = rem >> 9;
        int k = rem & 511;
        int s_ = sg / 3, g2 = sg % 3;
        int uu = c * 4 + sl;
        swd[i] = (s_ == 0) ? dWhh[((size_t)g2 * HD + uu) * HD + k]
                           : dWih[((size_t)(g2 * HD + uu)) * 768 + 256 + k];
    }
    int ws = which >> 1;
    int kb = (which & 1) * 256;
    const float4* vr = (const float4*)&swd[((ws * 3 + 0) * 4 + slot) * 512 + kb];
    const float4* vz = (const float4*)&swd[((ws * 3 + 1) * 4 + slot) * 512 + kb];
    const float4* vn = (const float4*)&swd[((ws * 3 + 2) * 4 + slot) * 512 + kb];
    float db_r = dbhh[gu], db_z = dbhh[HD + gu], db_n = dbhh[2 * HD + gu];
    unsigned* cnt = &g_bar_cnt[2];
    __syncthreads();

    for (int t = 0; t < TT; t++) {
        const float* hcur = g_hdec[t & 1];
        // ---- fill shh early (overlaps Phase A; separate smem region) ----
        for (int i4 = tid; i4 < BB * HD / 4; i4 += 512) {
            int b2 = i4 >> 7, k = (i4 & 127) * 4;
            *(float4*)&shh[b2 * DST + k] = __ldcg((const float4*)&hcur[i4 * 4]);
        }
        // ---------- Phase A: flash attention partials ----------
        {
            const float* hd = hcur + ab * HD;
            float4 hreg[4];
#pragma unroll
            for (int j = 0; j < 4; j++)
                hreg[j] = __ldcg((const float4*)(hd + (j * 32 + lane) * 4));
            const float* eb = g_enhy + (size_t)ab * SS * HD;
            float m = -1e30f, l = 0.f;
            float4 cacc[4];
#pragma unroll
            for (int j = 0; j < 4; j++) cacc[j] = make_float4(0.f, 0.f, 0.f, 0.f);
            for (int s = s0 + w; s < s0 + SS / 4; s += 16) {
                const float4* e4 = (const float4*)(eb + (size_t)s * HD);
                float4 ev[4];
                float acc = 0.f;
#pragma unroll
                for (int j = 0; j < 4; j++) {
                    ev[j] = __ldg(&e4[j * 32 + lane]);
                    acc += ev[j].x * hreg[j].x + ev[j].y * hreg[j].y
                         + ev[j].z * hreg[j].z + ev[j].w * hreg[j].w;
                }
#pragma unroll
                for (int o = 16; o; o >>= 1) acc += __shfl_xor_sync(0xffffffffu, acc, o);
                float mnew = fmaxf(m, acc);
                float scale = __expf(m - mnew);
                float p = __expf(acc - mnew);
                l = l * scale + p;
#pragma unroll
                for (int j = 0; j < 4; j++) {
                    cacc[j].x = cacc[j].x * scale + p * ev[j].x;
                    cacc[j].y = cacc[j].y * scale + p * ev[j].y;
                    cacc[j].z = cacc[j].z * scale + p * ev[j].z;
                    cacc[j].w = cacc[j].w * scale + p * ev[j].w;
                }
                m = mnew;
            }
            if (lane == 0) { sm_m[w] = m; sm_l[w] = l; }
#pragma unroll
            for (int j = 0; j < 4; j++)
                ((float4*)(sm_ctx + w * HD))[j * 32 + lane] = cacc[j];
            __syncthreads();
            float M = -1e30f;
#pragma unroll
            for (int q = 0; q < 16; q++) M = fmaxf(M, sm_m[q]);
            float L = 0.f, vv = 0.f;
            int e = tid;
#pragma unroll
            for (int q = 0; q < 16; q++) {
                float f_ = __expf(sm_m[q] - M);
                L += sm_l[q] * f_;
                vv += sm_ctx[q * HD + e] * f_;
            }
            g_attc[chunk][ab][e] = vv;
            if (tid == 0) { g_attm[chunk][ab] = M; g_attl[chunk][ab] = L; }
        }
        bar_sync(cnt, (unsigned)(128 * (3 * t + 1)));
        // ---------- Phase R: distributed combine ----------
        if (tid < 128) {
            int idx = c * 128 + tid;
            int b2 = idx >> 9, e = idx & 511;
            float m0 = __ldcg(&g_attm[0][b2]), m1 = __ldcg(&g_attm[1][b2]);
            float m2 = __ldcg(&g_attm[2][b2]), m3 = __ldcg(&g_attm[3][b2]);
            float M = fmaxf(fmaxf(m0, m1), fmaxf(m2, m3));
            float f0 = __expf(m0 - M), f1 = __expf(m1 - M);
            float f2 = __expf(m2 - M), f3 = __expf(m3 - M);
            float L = __ldcg(&g_attl[0][b2]) * f0 + __ldcg(&g_attl[1][b2]) * f1
                    + __ldcg(&g_attl[2][b2]) * f2 + __ldcg(&g_attl[3][b2]) * f3;
            float v = __ldcg(&g_attc[0][b2][e]) * f0 + __ldcg(&g_attc[1][b2][e]) * f1
                    + __ldcg(&g_attc[2][b2][e]) * f2 + __ldcg(&g_attc[3][b2][e]) * f3;
            g_ctx[b2 * HD + e] = fast_tanh(__fdividef(v, L));
        }
        bar_sync(cnt, (unsigned)(128 * (3 * t + 2)));
        // ---------- Phase G: GRU step ----------
        {
            for (int i4 = tid; i4 < BB * HD / 4; i4 += 512) {
                int b2 = i4 >> 7, k = (i4 & 127) * 4;
                *(float4*)&shc[b2 * DST + k] = __ldcg((const float4*)&g_ctx[i4 * 4]);
            }
            __syncthreads();
            const float* src = (ws ? shc : shh) + gb * DST + kb;
            float ar = 0.f, az = 0.f, an = 0.f;
#pragma unroll 8
            for (int k4 = 0; k4 < 64; k4++) {
                float4 h4 = *(const float4*)(src + k4 * 4);
                float4 ww;
                ww = vr[k4]; ar += h4.x * ww.x + h4.y * ww.y + h4.z * ww.z + h4.w * ww.w;
                ww = vz[k4]; az += h4.x * ww.x + h4.y * ww.y + h4.z * ww.z + h4.w * ww.w;
                ww = vn[k4]; an += h4.x * ww.x + h4.y * ww.y + h4.z * ww.z + h4.w * ww.w;
            }
            int p = tid & 127;
            if (which != 0) {
                smx[((which - 1) * 3 + 0) * 132 + p] = ar;
                smx[((which - 1) * 3 + 1) * 132 + p] = az;
                smx[((which - 1) * 3 + 2) * 132 + p] = an;
            }
            __syncthreads();
            if (which == 0) {
                float ar2 = ar + smx[0 * 132 + p];
                float az2 = az + smx[1 * 132 + p];
                float an2 = an + smx[2 * 132 + p];
                float cr = smx[3 * 132 + p] + smx[6 * 132 + p];
                float cz = smx[4 * 132 + p] + smx[7 * 132 + p];
                float cn = smx[5 * 132 + p] + smx[8 * 132 + p];
                const float* gi = g_gidec + ((size_t)t * BB + gb) * (3 * HD);
                float ghr = ar2 + db_r, ghz = az2 + db_z, ghn = an2 + db_n;
                float r = fast_sigmoid(__ldg(&gi[gu]) + cr + ghr);
                float z = fast_sigmoid(__ldg(&gi[HD + gu]) + cz + ghz);
                float n = fast_tanh(__ldg(&gi[2 * HD + gu]) + cn + r * ghn);
                float hp = shh[gb * DST + gu];
                float hn2 = (1.f - z) * n + z * hp;
                g_hdec[(t + 1) & 1][gb * HD + gu] = hn2;
                g_decout[((size_t)gb * TT + t) * HD + gu] = hn2;
            }
        }
        bar_sync(cnt, (unsigned)(128 * (3 * t + 3)));
    }
}

// ---------------- host ----------------
extern "C" void kernel_launch(void* const* d_in, const int* in_sizes, int n_in,
                              void* d_out, int out_size) {
    const int*   src_ids = (const int*)d_in[0];
    const int*   trg_ids = (const int*)d_in[1];
    const float* src_emb = (const float*)d_in[2];
    const float* trg_emb = (const float*)d_in[3];
    const float* eWihf   = (const float*)d_in[4];
    const float* eWhhf   = (const float*)d_in[5];
    const float* ebihf   = (const float*)d_in[6];
    const float* ebhhf   = (const float*)d_in[7];
    const float* eWihb   = (const float*)d_in[8];
    const float* eWhhb   = (const float*)d_in[9];
    const float* ebihb   = (const float*)d_in[10];
    const float* ebhhb   = (const float*)d_in[11];
    const float* e2dW    = (const float*)d_in[12];
    const float* e2db    = (const float*)d_in[13];
    const float* dWih    = (const float*)d_in[14];
    const float* dWhh    = (const float*)d_in[15];
    const float* dbih    = (const float*)d_in[16];
    const float* dbhh    = (const float*)d_in[17];
    const float* outW    = (const float*)d_in[18];
    const float* outb    = (const float*)d_in[19];
    float* out = (float*)d_out;

    const int ENC_SMEM = (6144 + 32 * EST) * (int)sizeof(float);                    // 58880
    const int DEC_SMEM = (12288 + 64 * DST + 1188 + 32 + 16 * 512) * (int)sizeof(float); // 220944
    cudaFuncSetAttribute(enc_persist, cudaFuncAttributeMaxDynamicSharedMemorySize, ENC_SMEM);
    cudaFuncSetAttribute(dec_persist, cudaFuncAttributeMaxDynamicSharedMemorySize, DEC_SMEM);

    float *p_srcx, *p_trgx, *p_gif, *p_gib, *p_gidec, *p_hcat, *p_hdec, *p_decout;
    cudaGetSymbolAddress((void**)&p_srcx, g_srcx);
    cudaGetSymbolAddress((void**)&p_trgx, g_trgx);
    cudaGetSymbolAddress((void**)&p_gif, g_gif);
    cudaGetSymbolAddress((void**)&p_gib, g_gib);
    cudaGetSymbolAddress((void**)&p_gidec, g_gidec);
    cudaGetSymbolAddress((void**)&p_hcat, g_hcat);
    cudaGetSymbolAddress((void**)&p_hdec, g_hdec);
    cudaGetSymbolAddress((void**)&p_decout, g_decout);

    // 1) embeddings + prep
    embed_kernel<<<(SS * BB * (EE / 4) + 255) / 256, 256>>>(src_ids, src_emb, p_srcx, SS);
    embed_kernel<<<(TT * BB * (EE / 4) + 255) / 256, 256>>>(trg_ids, trg_emb, p_trgx, TT);
    prep_kernel<<<(2 * BB * HE + 255) / 256, 256>>>();

    // 2) time-parallel input-side GRU GEMMs (tf32, K=256, 128x128 tiles)
    gemm_tf32<256><<<dim3(768 / 128, SS * BB / 128), 128>>>(p_srcx, eWihf, ebihf, p_gif, SS * BB, 768, 256);
    gemm_tf32<256><<<dim3(768 / 128, SS * BB / 128), 128>>>(p_srcx, eWihb, ebihb, p_gib, SS * BB, 768, 256);
    gemm_tf32<256><<<dim3(1536 / 128, TT * BB / 128), 128>>>(p_trgx, dWih, dbih, p_gidec, TT * BB, 1536, 768);

    // 3) persistent encoder scan (64 CTAs)
    enc_persist<<<64, 256, ENC_SMEM>>>(eWhhf, eWhhb, ebhhf, ebhhb);

    // 4) h0 = tanh([hT_f,hT_b] @ e2d_W.T + e2d_b)
    hcat_kernel<<<(BB * 2 * HE + 255) / 256, 256>>>();
    gemm_atb<<<dim3(512 / 64, 1), 256>>>(p_hcat, e2dW, e2db, p_hdec, BB, 512, 512, 512, 1);

    // 5) persistent decoder scan (3 barriers/step)
    dec_persist<<<128, 512, DEC_SMEM>>>(dWih, dWhh, dbhh);

    // 6) logits = dec_out @ out_W.T + out_b (tf32, K=512, 128x128 tiles)
    gemm_tf32<512><<<dim3(VV / 128, BB * TT / 128), 128>>>(p_decout, outW, outb, out, BB * TT, VV, 512);
}